// round 5
// baseline (speedup 1.0000x reference)
#include <cuda_runtime.h>
#include <cstdint>

// CrfHead: out[b,t,:] = x[b,t,:] + transitions[argmax(x[b,t,:]), :]
// 131072 rows x 256 floats. cp.async multistage pipeline: loads stream into
// smem independent of the compute chain, so DRAM reads stay in flight while
// warps sit in the argmax -> L2-gather -> store tail.

#define TAGS 256
#define ROWS (128 * 1024)
#define THREADS 256            // 8 warps
#define RPS 8                  // rows per stage (1 per warp)
#define NSTAGES 4              // 4 x 8KB = 32KB smem
#define NSTEPS 8               // steps per block
#define ROWS_PER_BLOCK (RPS * NSTEPS)        // 64
#define BLOCKS (ROWS / ROWS_PER_BLOCK)       // 2048
#define F4_PER_ROW (TAGS / 4)                // 64
#define F4_PER_STAGE (RPS * F4_PER_ROW)      // 512

__device__ __forceinline__ void cp_async16(float4* smem_dst, const float4* gmem_src) {
    uint32_t s = (uint32_t)__cvta_generic_to_shared(smem_dst);
    asm volatile("cp.async.cg.shared.global [%0], [%1], 16;\n" :: "r"(s), "l"(gmem_src));
}
__device__ __forceinline__ void cp_commit() {
    asm volatile("cp.async.commit_group;\n" ::: "memory");
}
template <int N>
__device__ __forceinline__ void cp_wait() {
    asm volatile("cp.async.wait_group %0;\n" :: "n"(N) : "memory");
}

// Monotone float -> uint32 map (total order matches float <; no NaNs in input).
__device__ __forceinline__ unsigned ford(float f) {
    unsigned u = __float_as_uint(f);
    return (u >> 31) ? ~u : (u | 0x80000000u);
}

__global__ __launch_bounds__(THREADS)
void crf_head_kernel(const float4* __restrict__ x,
                     const float* __restrict__ trans,
                     float4* __restrict__ out) {
    __shared__ float4 buf[NSTAGES][F4_PER_STAGE];

    const int tid  = threadIdx.x;
    const int warp = tid >> 5;
    const int lane = tid & 31;

    // Block's slice: 64 contiguous rows.
    const size_t row0   = (size_t)blockIdx.x * ROWS_PER_BLOCK;
    const float4* gx    = x + row0 * F4_PER_ROW;
    float4*       gout  = out + row0 * F4_PER_ROW;

    // Prologue: issue stages 0 .. NSTAGES-2.
    #pragma unroll
    for (int s = 0; s < NSTAGES - 1; s++) {
        const float4* src = gx + (size_t)s * F4_PER_STAGE;
        cp_async16(&buf[s][tid],       src + tid);
        cp_async16(&buf[s][tid + 256], src + tid + 256);
        cp_commit();
    }

    for (int step = 0; step < NSTEPS; step++) {
        // Issue stage step+NSTAGES-1 into buf[(step-1)%NSTAGES] (processed at
        // step-1; post-compute barrier below guarantees it is free).
        const int fs = step + NSTAGES - 1;
        if (fs < NSTEPS) {
            const int sb = fs % NSTAGES;
            const float4* src = gx + (size_t)fs * F4_PER_STAGE;
            cp_async16(&buf[sb][tid],       src + tid);
            cp_async16(&buf[sb][tid + 256], src + tid + 256);
        }
        cp_commit();  // commit every iter so group counting stays uniform

        cp_wait<NSTAGES - 1>();   // stage `step` complete (per-thread)
        __syncthreads();          // make it visible block-wide

        // Warp w processes row w of this stage.
        const float4* rowp = &buf[step % NSTAGES][warp * F4_PER_ROW];
        const float4 a = rowp[lane];
        const float4 b = rowp[lane + 32];

        // Lane-local argmax over 8 elems; strict > keeps lowest index.
        const int i0 = lane * 4, i1 = (lane + 32) * 4;
        float v = a.x; int idx = i0;
        if (a.y > v) { v = a.y; idx = i0 + 1; }
        if (a.z > v) { v = a.z; idx = i0 + 2; }
        if (a.w > v) { v = a.w; idx = i0 + 3; }
        if (b.x > v) { v = b.x; idx = i1;     }
        if (b.y > v) { v = b.y; idx = i1 + 1; }
        if (b.z > v) { v = b.z; idx = i1 + 2; }
        if (b.w > v) { v = b.w; idx = i1 + 3; }

        // Warp argmax: REDUX.MAX on ordered key, REDUX.MIN on candidate index.
        const unsigned k = ford(v);
        const unsigned m = __reduce_max_sync(0xFFFFFFFFu, k);
        const unsigned cand = (k == m) ? (unsigned)idx : 0xFFFFu;
        const int best = (int)__reduce_min_sync(0xFFFFFFFFu, cand);

        // transitions row: 256KB working set, L2-resident.
        const float4* trow = reinterpret_cast<const float4*>(trans + (size_t)best * TAGS);
        const float4 t0 = __ldg(&trow[lane]);
        const float4 t1 = __ldg(&trow[lane + 32]);

        const size_t obase = ((size_t)step * RPS + warp) * F4_PER_ROW;
        float4 r;
        r.x = a.x + t0.x; r.y = a.y + t0.y; r.z = a.z + t0.z; r.w = a.w + t0.w;
        __stcs(&gout[obase + lane], r);
        r.x = b.x + t1.x; r.y = b.y + t1.y; r.z = b.z + t1.z; r.w = b.w + t1.w;
        __stcs(&gout[obase + lane + 32], r);

        __syncthreads();          // all warps done reading stage before reuse
    }
}

extern "C" void kernel_launch(void* const* d_in, const int* in_sizes, int n_in,
                              void* d_out, int out_size) {
    const float4* x     = reinterpret_cast<const float4*>(d_in[0]);
    const float*  trans = reinterpret_cast<const float*>(d_in[1]);
    float4*       out   = reinterpret_cast<float4*>(d_out);

    crf_head_kernel<<<BLOCKS, THREADS>>>(x, trans, out);
}